// round 13
// baseline (speedup 1.0000x reference)
#include <cuda_runtime.h>
#include <cuda_bf16.h>
#include <cuda_fp16.h>
#include <math.h>
#include <stdint.h>

#define K_DIM 256
#define HD 128
#define MAX_N 100000
#define MAX_E 1600000

// ---------------- scratch (static device arrays; no allocation) ----------------
__device__ __half g_xwh[(size_t)MAX_N * HD];      // x @ lin_l^T + b (fp16) [N,128]
__device__ float g_s1[(size_t)MAX_N * 4];         // a1 logits per node [N,4]
__device__ float g_s2[(size_t)MAX_N * 4];         // a2 logits per node [N,4]
__device__ int   g_off[MAX_N + 1];                // CSR offsets
__device__ __nv_bfloat16 g_bh[272 * 256];         // logits weights hi (rows 256..263 used)
__device__ __nv_bfloat16 g_bl[272 * 256];         // logits weights lo
__device__ float g_bc[272];                       // bias cat (264 used)
// B fragments in mma.m16n8k16 b-layout: [by][s(16)][t(16)][lane(32)][r(2)] uint32
__device__ uint32_t g_bfh[2 * 16 * 16 * 32 * 2];
__device__ uint32_t g_bfl[2 * 16 * 16 * 32 * 2];

// ---------------- PTX helpers ---------------------------------------------------
__device__ __forceinline__ uint32_t smem_u32(const void* p) {
    uint32_t a;
    asm("{ .reg .u64 t; cvta.to.shared.u64 t, %1; cvt.u32.u64 %0, t; }" : "=r"(a) : "l"(p));
    return a;
}
__device__ __forceinline__ void ldsm4(uint32_t* r, uint32_t addr) {
    asm volatile("ldmatrix.sync.aligned.m8n8.x4.shared.b16 {%0,%1,%2,%3}, [%4];"
                 : "=r"(r[0]), "=r"(r[1]), "=r"(r[2]), "=r"(r[3]) : "r"(addr));
}
__device__ __forceinline__ void ldsm2(uint32_t* r, uint32_t addr) {
    asm volatile("ldmatrix.sync.aligned.m8n8.x2.shared.b16 {%0,%1}, [%2];"
                 : "=r"(r[0]), "=r"(r[1]) : "r"(addr));
}
__device__ __forceinline__ void mma_bf16(float* c, const uint32_t* a, uint32_t b0, uint32_t b1) {
    asm volatile(
        "mma.sync.aligned.m16n8k16.row.col.f32.bf16.bf16.f32 "
        "{%0,%1,%2,%3}, {%4,%5,%6,%7}, {%8,%9}, {%0,%1,%2,%3};"
        : "+f"(c[0]), "+f"(c[1]), "+f"(c[2]), "+f"(c[3])
        : "r"(a[0]), "r"(a[1]), "r"(a[2]), "r"(a[3]), "r"(b0), "r"(b1));
}

// ---------------- weight prep A: logits weight rows + biases ---------------------
__global__ void wprep_k(const float* __restrict__ llb, const float* __restrict__ lrb,
                        const float* __restrict__ a1w, const float* __restrict__ a1b,
                        const float* __restrict__ a2w, const float* __restrict__ a2b)
{
    const int idx = blockIdx.x * blockDim.x + threadIdx.x;
    if (idx < 2048) {   // rows 256..263 of concat weights = a1 (4) | a2 (4)
        const int r = idx >> 8, k = idx & 255;
        const float v = (r < 4) ? a1w[r * 256 + k] : a2w[(r - 4) * 256 + k];
        const __nv_bfloat16 hi = __float2bfloat16(v);
        g_bh[(256 + r) * 256 + k] = hi;
        g_bl[(256 + r) * 256 + k] = __float2bfloat16(v - __bfloat162float(hi));
    } else if (idx < 2048 + 264) {
        const int b = idx - 2048;
        float v;
        if      (b < 128) v = llb[b];
        else if (b < 256) v = lrb[b - 128];
        else if (b < 260) v = a1b[b - 256];
        else              v = a2b[b - 260];
        g_bc[b] = v;
    }
}

// ---------------- weight prep B: fragment-order hi/lo ----------------------------
__global__ void frag_k(const float* __restrict__ llw, const float* __restrict__ lrw)
{
    const int idx = blockIdx.x * blockDim.x + threadIdx.x;   // 0..65535
    const int r = idx & 1;
    const int l = (idx >> 1) & 31;
    const int t = (idx >> 6) & 15;
    const int s = (idx >> 10) & 15;
    const int by = idx >> 14;
    const int ng = by * 128 + t * 8 + (l >> 2);
    const int k0 = s * 16 + (l & 3) * 2 + 8 * r;
    const float* w = (ng < 128) ? (llw + ng * 256) : (lrw + (ng - 128) * 256);
    const float v0 = w[k0], v1 = w[k0 + 1];
    const __nv_bfloat16 h0 = __float2bfloat16(v0);
    const __nv_bfloat16 h1 = __float2bfloat16(v1);
    const __nv_bfloat16 l0 = __float2bfloat16(v0 - __bfloat162float(h0));
    const __nv_bfloat16 l1 = __float2bfloat16(v1 - __bfloat162float(h1));
    uint32_t hp, lp;
    asm("mov.b32 %0, {%1, %2};" : "=r"(hp) : "h"(*(const uint16_t*)&h0), "h"(*(const uint16_t*)&h1));
    asm("mov.b32 %0, {%1, %2};" : "=r"(lp) : "h"(*(const uint16_t*)&l0), "h"(*(const uint16_t*)&l1));
    g_bfh[idx] = hp;
    g_bfl[idx] = lp;
}

// ---------------- HMMA bf16-split GEMM (direct-LDG B) + fused logits -------------
#define LDS_STRIDE 40

__global__ void __launch_bounds__(256, 2)
gemm_mma_k(const float* __restrict__ A, float* __restrict__ outp, int M)
{
    __shared__ __align__(16) __nv_bfloat16 Ah[128 * LDS_STRIDE];
    __shared__ __align__(16) __nv_bfloat16 Al[128 * LDS_STRIDE];
    __shared__ __align__(16) __nv_bfloat16 Bxh[8 * LDS_STRIDE];
    __shared__ __align__(16) __nv_bfloat16 Bxl[8 * LDS_STRIDE];
    __shared__ float s_acc[128 * 9];

    const int tid = threadIdx.x;
    const int wid = tid >> 5;
    const int lane = tid & 31;
    const int bm = blockIdx.x * 128;
    const int by = blockIdx.y;
    const int warp_m = wid & 3;
    const int warp_n = wid >> 2;

    for (int i = tid; i < 128 * 9; i += 256) s_acc[i] = 0.f;

    float acc[2][8][4];
#pragma unroll
    for (int i = 0; i < 2; i++)
#pragma unroll
        for (int j = 0; j < 8; j++)
#pragma unroll
            for (int q = 0; q < 4; q++) acc[i][j][q] = 0.f;

    const int lrow = tid >> 1;
    const int lhalf = tid & 1;
    const bool avalid = (bm + lrow) < M;
    const float* ag = A + (size_t)(bm + lrow) * K_DIM + lhalf * 16;
    const __nv_bfloat16* bgxh = g_bh + (size_t)(256 + (tid >> 1)) * 256 + lhalf * 16;
    const __nv_bfloat16* bgxl = g_bl + (size_t)(256 + (tid >> 1)) * 256 + lhalf * 16;

    // B fragment base for this warp: uint2 index = ((by*16+s)*16 + warp_n*8+nt)*32 + lane
    const uint2* bfh = (const uint2*)g_bfh + ((size_t)by * 256 + warp_n * 8) * 32 + lane;
    const uint2* bfl = (const uint2*)g_bfl + ((size_t)by * 256 + warp_n * 8) * 32 + lane;

    const uint32_t ah_s = smem_u32(Ah);
    const uint32_t al_s = smem_u32(Al);
    const uint32_t bxh_s = smem_u32(Bxh);
    const uint32_t bxl_s = smem_u32(Bxl);

    char* ah_p = (char*)Ah; char* al_p = (char*)Al;
    char* bxh_p = (char*)Bxh; char* bxl_p = (char*)Bxl;
    const uint32_t st_off = lrow * (LDS_STRIDE * 2) + lhalf * 32;

    for (int c = 0; c < 8; c++) {
        if (c) __syncthreads();

        // ---- A chunk: fp32 -> bf16 hi/lo (128 rows x 32 k) ----
#pragma unroll
        for (int q = 0; q < 4; q++) {
            float4 f = avalid ? *(const float4*)(ag + c * 32 + q * 4) : make_float4(0, 0, 0, 0);
            __nv_bfloat162 h0 = __floats2bfloat162_rn(f.x, f.y);
            __nv_bfloat162 h1 = __floats2bfloat162_rn(f.z, f.w);
            float2 fh0 = __bfloat1622float2(h0), fh1 = __bfloat1622float2(h1);
            __nv_bfloat162 l0 = __floats2bfloat162_rn(f.x - fh0.x, f.y - fh0.y);
            __nv_bfloat162 l1 = __floats2bfloat162_rn(f.z - fh1.x, f.w - fh1.y);
            uint2 hv, lv;
            hv.x = *(uint32_t*)&h0; hv.y = *(uint32_t*)&h1;
            lv.x = *(uint32_t*)&l0; lv.y = *(uint32_t*)&l1;
            *(uint2*)(ah_p + st_off + q * 8) = hv;
            *(uint2*)(al_p + st_off + q * 8) = lv;
        }
        if (by == 0 && tid < 16) {
            const uint4* sh = (const uint4*)(bgxh + c * 32);
            const uint4* sl = (const uint4*)(bgxl + c * 32);
            *(uint4*)(bxh_p + st_off)      = sh[0];
            *(uint4*)(bxh_p + st_off + 16) = sh[1];
            *(uint4*)(bxl_p + st_off)      = sl[0];
            *(uint4*)(bxl_p + st_off + 16) = sl[1];
        }
        __syncthreads();

        float cx[2][4] = {{0.f, 0.f, 0.f, 0.f}, {0.f, 0.f, 0.f, 0.f}};

#pragma unroll
        for (int ks = 0; ks < 2; ks++) {
            const int s = c * 2 + ks;
            // B fragments: 16 independent LDG.64 (L1/L2-hot)
            uint2 bh2[8], bl2[8];
#pragma unroll
            for (int nt = 0; nt < 8; nt++) {
                bh2[nt] = bfh[(size_t)(s * 16 + nt) * 32];
                bl2[nt] = bfl[(size_t)(s * 16 + nt) * 32];
            }
            const uint32_t kb = ks * 32 + (lane >> 4) * 16;
            uint32_t a_h[2][4], a_l[2][4];
#pragma unroll
            for (int mt = 0; mt < 2; mt++) {
                const uint32_t ro = (warp_m * 32 + mt * 16 + (lane & 15)) * (LDS_STRIDE * 2) + kb;
                ldsm4(a_h[mt], ah_s + ro);
                ldsm4(a_l[mt], al_s + ro);
            }
#pragma unroll
            for (int nt = 0; nt < 8; nt++) {
#pragma unroll
                for (int mt = 0; mt < 2; mt++) {
                    mma_bf16(acc[mt][nt], a_h[mt], bh2[nt].x, bh2[nt].y);
                    mma_bf16(acc[mt][nt], a_h[mt], bl2[nt].x, bl2[nt].y);
                    mma_bf16(acc[mt][nt], a_l[mt], bh2[nt].x, bh2[nt].y);
                }
            }
            if (by == 0 && warp_n == 0) {
                const int la = lane & 15;
                const uint32_t rox = (la & 7) * (LDS_STRIDE * 2) + ((la >> 3) & 1) * 16 + ks * 32;
                uint32_t bx_h[2], bx_l[2];
                ldsm2(bx_h, bxh_s + rox);
                ldsm2(bx_l, bxl_s + rox);
#pragma unroll
                for (int mt = 0; mt < 2; mt++) {
                    mma_bf16(cx[mt], a_h[mt], bx_h[0], bx_h[1]);
                    mma_bf16(cx[mt], a_h[mt], bx_l[0], bx_l[1]);
                    mma_bf16(cx[mt], a_l[mt], bx_h[0], bx_h[1]);
                }
            }
        }
        if (by == 0 && warp_n == 0) {
#pragma unroll
            for (int mt = 0; mt < 2; mt++) {
                const int r = warp_m * 32 + mt * 16 + (lane >> 2);
                const int cc = (lane & 3) * 2;
                s_acc[r * 9 + cc]           += cx[mt][0];
                s_acc[r * 9 + cc + 1]       += cx[mt][1];
                s_acc[(r + 8) * 9 + cc]     += cx[mt][2];
                s_acc[(r + 8) * 9 + cc + 1] += cx[mt][3];
            }
        }
    }

    if (by == 0) {
#pragma unroll
        for (int mt = 0; mt < 2; mt++) {
            const int r0 = bm + warp_m * 32 + mt * 16 + (lane >> 2);
#pragma unroll
            for (int j = 0; j < 8; j++) {
                const int cc = warp_n * 64 + j * 8 + (lane & 3) * 2;
                const float b0 = g_bc[cc], b1 = g_bc[cc + 1];
                if (r0 < M)
                    *(__half2*)(g_xwh + (size_t)r0 * HD + cc) =
                        __floats2half2_rn(acc[mt][j][0] + b0, acc[mt][j][1] + b1);
                if (r0 + 8 < M)
                    *(__half2*)(g_xwh + (size_t)(r0 + 8) * HD + cc) =
                        __floats2half2_rn(acc[mt][j][2] + b0, acc[mt][j][3] + b1);
            }
        }
        __syncthreads();
#pragma unroll
        for (int it = 0; it < 4; it++) {
            const int idx = tid + it * 256;
            const int r = idx >> 3, cc = idx & 7;
            const int gr = bm + r;
            if (gr < M) {
                const float v = s_acc[r * 9 + cc] + g_bc[256 + cc];
                if (cc < 4) g_s1[(size_t)gr * 4 + cc] = v;
                else        g_s2[(size_t)gr * 4 + cc - 4] = v;
            }
        }
    } else {
        const float* bias = g_bc + 128;
#pragma unroll
        for (int mt = 0; mt < 2; mt++) {
            const int r0 = bm + warp_m * 32 + mt * 16 + (lane >> 2);
#pragma unroll
            for (int j = 0; j < 8; j++) {
                const int cc = warp_n * 64 + j * 8 + (lane & 3) * 2;
                const float b0 = bias[cc], b1 = bias[cc + 1];
                if (r0 < M)
                    *(float2*)(outp + (size_t)r0 * HD + cc) =
                        make_float2(acc[mt][j][0] + b0, acc[mt][j][1] + b1);
                if (r0 + 8 < M)
                    *(float2*)(outp + (size_t)(r0 + 8) * HD + cc) =
                        make_float2(acc[mt][j][2] + b0, acc[mt][j][3] + b1);
            }
        }
    }
}

// ---------------- CSR offsets (windowed binary search + fallback) ---------------
__global__ void offsets_k(const int* __restrict__ row, int n, int e)
{
    const int i = blockIdx.x * blockDim.x + threadIdx.x;
    if (i > n) return;
    const int g = (int)((long long)i * e / n);
    int lo = g - 4096; if (lo < 0) lo = 0;
    int hi = g + 4096; if (hi > e) hi = e;
    const bool ok_lo = (lo == 0) || (row[lo - 1] < i);
    const bool ok_hi = (hi == e) || (row[hi - 1] >= i);
    if (!(ok_lo && ok_hi)) { lo = 0; hi = e; }
    while (lo < hi) {
        const int mid = (lo + hi) >> 1;
        if (row[mid] < i) lo = mid + 1; else hi = mid;
    }
    g_off[i] = lo;
}

// ---------------- segment softmax + aggregation (MLP-8 pipelined gather) --------
__global__ void __launch_bounds__(256)
agg_k(const int* __restrict__ col, float* __restrict__ out, int n)
{
    __shared__ float sw[8][32][4];   // [warp][edge][head]
    __shared__ int   sc[8][32];      // [warp][edge]

    const int wl = threadIdx.x >> 5;
    const int warp_id = (blockIdx.x * blockDim.x + threadIdx.x) >> 5;
    const int lane = threadIdx.x & 31;
    if (warp_id >= n) return;

    const int e0 = g_off[warp_id];
    const int e1 = g_off[warp_id + 1];
    if (e0 >= e1) return;

    const float4 s14 = *(const float4*)(g_s1 + (size_t)warp_id * 4);
    const int head = lane >> 3;

    float m0 = -INFINITY, m1 = -INFINITY, m2 = -INFINITY, m3 = -INFINITY;
    float sum0 = 0.f, sum1 = 0.f, sum2 = 0.f, sum3 = 0.f;
    float acc0 = 0.f, acc1 = 0.f, acc2 = 0.f, acc3 = 0.f;

    for (int blk = e0; blk < e1; blk += 32) {
        const int idx = blk + lane;
        const bool v = idx < e1;
        const int c_own = v ? col[idx] : 0;

        float a0 = -INFINITY, a1 = -INFINITY, a2 = -INFINITY, a3 = -INFINITY;
        if (v) {
            const float4 s2v = *(const float4*)(g_s2 + (size_t)c_own * 4);
            a0 = s14.x + s2v.x; a1 = s14.y + s2v.y;
            a2 = s14.z + s2v.z; a3 = s14.w + s2v.w;
        }

        float b0 = a0, b1 = a1, b2 = a2, b3 = a3;
#pragma unroll
        for (int o = 16; o; o >>= 1) {
            b0 = fmaxf(b0, __shfl_xor_sync(0xffffffffu, b0, o));
            b1 = fmaxf(b1, __shfl_xor_sync(0xffffffffu, b1, o));
            b2 = fmaxf(b2, __shfl_xor_sync(0xffffffffu, b2, o));
            b3 = fmaxf(b3, __shfl_xor_sync(0xffffffffu, b3, o));
        }
        const float n0 = fmaxf(m0, b0), n1 = fmaxf(m1, b1);
        const float n2 = fmaxf(m2, b2), n3 = fmaxf(m3, b3);

        const float r0 = __expf(m0 - n0), r1 = __expf(m1 - n1);
        const float r2 = __expf(m2 - n2), r3 = __expf(m3 - n3);
        m0 = n0; m1 = n1; m2 = n2; m3 = n3;
        sum0 *= r0; sum1 *= r1; sum2 *= r2; sum3 *= r3;
        const float rsel = (head == 0) ? r0 : (head == 1) ? r1 : (head == 2) ? r2 : r3;
        acc0 *= rsel; acc1 *= rsel; acc2 *= rsel; acc3 *= rsel;

        const float p0 = __expf(a0 - m0), p1 = __expf(a1 - m1);
        const float p2 = __expf(a2 - m2), p3 = __expf(a3 - m3);
        sum0 += p0; sum1 += p1; sum2 += p2; sum3 += p3;

        sc[wl][lane] = c_own;
        *(float4*)&sw[wl][lane][0] = make_float4(p0, p1, p2, p3);
        __syncwarp();

        const int nb = min(32, e1 - blk);
        for (int j0 = 0; j0 < nb; j0 += 8) {
            const int jn = min(8, nb - j0);
            uint2 u[8]; float wv[8];
#pragma unroll
            for (int j = 0; j < 8; j++) {
                if (j < jn) {
                    const int c = sc[wl][j0 + j];
                    wv[j] = sw[wl][j0 + j][head];
                    u[j] = *((const uint2*)(g_xwh + (size_t)c * HD) + lane);
                }
            }
#pragma unroll
            for (int j = 0; j < 8; j++) {
                if (j < jn) {
                    const float2 f0 = __half22float2(*(const __half2*)&u[j].x);
                    const float2 f1 = __half22float2(*(const __half2*)&u[j].y);
                    acc0 = fmaf(wv[j], f0.x, acc0);
                    acc1 = fmaf(wv[j], f0.y, acc1);
                    acc2 = fmaf(wv[j], f1.x, acc2);
                    acc3 = fmaf(wv[j], f1.y, acc3);
                }
            }
        }
        __syncwarp();
    }

#pragma unroll
    for (int o = 16; o; o >>= 1) {
        sum0 += __shfl_xor_sync(0xffffffffu, sum0, o);
        sum1 += __shfl_xor_sync(0xffffffffu, sum1, o);
        sum2 += __shfl_xor_sync(0xffffffffu, sum2, o);
        sum3 += __shfl_xor_sync(0xffffffffu, sum3, o);
    }
    const float ssel = (head == 0) ? sum0 : (head == 1) ? sum1 : (head == 2) ? sum2 : sum3;
    const float inv = 1.f / (ssel + 1e-16f);

    float* o = out + (size_t)warp_id * HD + lane * 4;
    float4 cv = *(float4*)o;
    cv.x += acc0 * inv; cv.y += acc1 * inv;
    cv.z += acc2 * inv; cv.w += acc3 * inv;
    *(float4*)o = cv;
}

// ---------------- launch ---------------------------------------------------------
extern "C" void kernel_launch(void* const* d_in, const int* in_sizes, int n_in,
                              void* d_out, int out_size)
{
    const float* x   = (const float*)d_in[0];
    const int*   row = (const int*)d_in[1];
    const int*   col = (const int*)d_in[2];
    const float* a1w = (const float*)d_in[3];
    const float* a1b = (const float*)d_in[4];
    const float* a2w = (const float*)d_in[5];
    const float* a2b = (const float*)d_in[6];
    const float* llw = (const float*)d_in[7];
    const float* llb = (const float*)d_in[8];
    const float* lrw = (const float*)d_in[9];
    const float* lrb = (const float*)d_in[10];

    const int n = in_sizes[0] / K_DIM;
    const int e = in_sizes[1];
    float* outp = (float*)d_out;

    wprep_k<<<10, 256>>>(llb, lrb, a1w, a1b, a2w, a2b);
    frag_k<<<256, 256>>>(llw, lrw);
    offsets_k<<<(n + 1 + 255) / 256, 256>>>(row, n, e);
    dim3 gg((n + 127) / 128, 2);
    gemm_mma_k<<<gg, 256>>>(x, outp, n);
    agg_k<<<(n * 32 + 255) / 256, 256>>>(col, outp, n);
}